// round 1
// baseline (speedup 1.0000x reference)
#include <cuda_runtime.h>
#include <math.h>

#define N_CLASSES 1000
#define EMBED     1024
#define THREADS   256

__global__ void zero_out_kernel(float* out) {
    out[0] = 0.0f;
}

__global__ void __launch_bounds__(THREADS)
angular_loss_kernel(const float* __restrict__ features,
                    const float* __restrict__ labels,
                    const float* __restrict__ mean_class,
                    float* __restrict__ out,
                    int N)
{
    const int row = blockIdx.x;
    const int tid = threadIdx.x;

    __shared__ int   s_idx;
    __shared__ float s_val;
    __shared__ float s_red[3][8];   // per-warp partials: ff, pp, fp

    if (tid == 0) { s_idx = 0; s_val = 0.0f; }
    __syncthreads();

    // ---- Phase 1: find the one-hot (index, value) in labels[row] ----
    // 1000 floats = 250 float4; row stride 4000 B is 16B-aligned.
    const float4* lrow = reinterpret_cast<const float4*>(
        labels + (size_t)row * N_CLASSES);
    #pragma unroll
    for (int i = tid; i < N_CLASSES / 4; i += THREADS) {
        float4 lv = lrow[i];
        if (lv.x != 0.0f) { s_idx = 4 * i + 0; s_val = lv.x; }
        if (lv.y != 0.0f) { s_idx = 4 * i + 1; s_val = lv.y; }
        if (lv.z != 0.0f) { s_idx = 4 * i + 2; s_val = lv.z; }
        if (lv.w != 0.0f) { s_idx = 4 * i + 3; s_val = lv.w; }
    }
    __syncthreads();

    const int   c = s_idx;
    const float v = s_val;

    // ---- Phase 2: dot products over embed_dim = 1024 (one float4/thread) ----
    const float4 f = reinterpret_cast<const float4*>(
        features + (size_t)row * EMBED)[tid];
    const float4 m = reinterpret_cast<const float4*>(
        mean_class + (size_t)c * EMBED)[tid];

    float ff = f.x * f.x + f.y * f.y + f.z * f.z + f.w * f.w;
    float pp = m.x * m.x + m.y * m.y + m.z * m.z + m.w * m.w;
    float fp = f.x * m.x + f.y * m.y + f.z * m.z + f.w * m.w;

    // warp reduce
    #pragma unroll
    for (int off = 16; off > 0; off >>= 1) {
        ff += __shfl_xor_sync(0xFFFFFFFF, ff, off);
        pp += __shfl_xor_sync(0xFFFFFFFF, pp, off);
        fp += __shfl_xor_sync(0xFFFFFFFF, fp, off);
    }
    const int lane = tid & 31;
    const int warp = tid >> 5;
    if (lane == 0) {
        s_red[0][warp] = ff;
        s_red[1][warp] = pp;
        s_red[2][warp] = fp;
    }
    __syncthreads();

    if (warp == 0) {
        ff = (lane < 8) ? s_red[0][lane] : 0.0f;
        pp = (lane < 8) ? s_red[1][lane] : 0.0f;
        fp = (lane < 8) ? s_red[2][lane] : 0.0f;
        #pragma unroll
        for (int off = 4; off > 0; off >>= 1) {
            ff += __shfl_xor_sync(0xFFFFFFFF, ff, off);
            pp += __shfl_xor_sync(0xFFFFFFFF, pp, off);
            fp += __shfl_xor_sync(0xFFFFFFFF, fp, off);
        }
        if (lane == 0) {
            const float eps = 1e-12f;
            float nf = fmaxf(sqrtf(ff), eps);
            float np = fmaxf(fabsf(v) * sqrtf(pp), eps);
            float cosv = (v * fp) / (nf * np);
            atomicAdd(out, (1.0f - cosv) / (float)N);
        }
    }
}

extern "C" void kernel_launch(void* const* d_in, const int* in_sizes, int n_in,
                              void* d_out, int out_size)
{
    const float* features   = (const float*)d_in[0];
    const float* labels     = (const float*)d_in[1];
    const float* mean_class = (const float*)d_in[2];
    float* out = (float*)d_out;

    const int N = in_sizes[0] / EMBED;   // 32768

    zero_out_kernel<<<1, 1>>>(out);
    angular_loss_kernel<<<N, THREADS>>>(features, labels, mean_class, out, N);
}

// round 2
// speedup vs baseline: 1.3004x; 1.3004x over previous
#include <cuda_runtime.h>
#include <math.h>

#define N_CLASSES 1000
#define L4        250          // label row in float4s (1000/4)
#define EMBED     1024
#define THREADS   256
#define WPB       8            // warps (rows) per block

__device__ float g_proto_norm[N_CLASSES];

// Prologue: one warp per class computes ||mean_class[c]||; also zeros out[0].
// Pre-warms mean_class into L2 as a side effect.
__global__ void proto_norm_kernel(const float* __restrict__ mean_class,
                                  float* __restrict__ out)
{
    if (blockIdx.x == 0 && threadIdx.x == 0) out[0] = 0.0f;
    const int warp = (blockIdx.x * blockDim.x + threadIdx.x) >> 5;
    const int lane = threadIdx.x & 31;
    if (warp >= N_CLASSES) return;

    const float4* row = reinterpret_cast<const float4*>(
        mean_class + (size_t)warp * EMBED);
    float pp = 0.0f;
    #pragma unroll
    for (int k = 0; k < 8; k++) {
        float4 m = __ldg(&row[k * 32 + lane]);
        pp += m.x*m.x + m.y*m.y + m.z*m.z + m.w*m.w;
    }
    #pragma unroll
    for (int off = 16; off > 0; off >>= 1)
        pp += __shfl_xor_sync(0xFFFFFFFFu, pp, off);
    if (lane == 0) g_proto_norm[warp] = sqrtf(pp);
}

__global__ void __launch_bounds__(THREADS)
angular_loss_kernel(const float* __restrict__ features,
                    const float* __restrict__ labels,
                    const float* __restrict__ mean_class,
                    float* __restrict__ out,
                    int N)
{
    const int warp = threadIdx.x >> 5;
    const int lane = threadIdx.x & 31;
    const int row  = blockIdx.x * WPB + warp;

    __shared__ float s_part[WPB];

    // ---- issue all independent loads up front (MLP ~16/thread) ----
    const float4* lrow = reinterpret_cast<const float4*>(
        labels + (size_t)row * N_CLASSES);
    float4 lv[8];
    #pragma unroll
    for (int k = 0; k < 8; k++) {
        const int idx = k * 32 + lane;
        lv[k] = (idx < L4) ? __ldcs(&lrow[idx]) : make_float4(0.f, 0.f, 0.f, 0.f);
    }

    const float4* frow = reinterpret_cast<const float4*>(
        features + (size_t)row * EMBED);
    float4 fv[8];
    #pragma unroll
    for (int k = 0; k < 8; k++)
        fv[k] = __ldcs(&frow[k * 32 + lane]);

    // ---- find the one-hot (index, value) in this row's labels ----
    int   c_loc = -1;
    float v_loc = 0.0f;
    #pragma unroll
    for (int k = 0; k < 8; k++) {
        const int base = (k * 32 + lane) * 4;
        if (lv[k].x != 0.0f) { c_loc = base + 0; v_loc = lv[k].x; }
        if (lv[k].y != 0.0f) { c_loc = base + 1; v_loc = lv[k].y; }
        if (lv[k].z != 0.0f) { c_loc = base + 2; v_loc = lv[k].z; }
        if (lv[k].w != 0.0f) { c_loc = base + 3; v_loc = lv[k].w; }
    }
    const unsigned found = __ballot_sync(0xFFFFFFFFu, c_loc >= 0);
    const int src = found ? (__ffs(found) - 1) : 0;
    int   c = __shfl_sync(0xFFFFFFFFu, c_loc, src);
    float v = __shfl_sync(0xFFFFFFFFu, v_loc, src);
    if (c < 0) { c = 0; v = 0.0f; }

    // ---- dot products; mean_class row is L2-hot ----
    const float4* mrow = reinterpret_cast<const float4*>(
        mean_class + (size_t)c * EMBED);
    float ff = 0.0f, fp = 0.0f;
    #pragma unroll
    for (int k = 0; k < 8; k++) {
        const float4 m = __ldg(&mrow[k * 32 + lane]);
        const float4 f = fv[k];
        ff += f.x*f.x + f.y*f.y + f.z*f.z + f.w*f.w;
        fp += f.x*m.x + f.y*m.y + f.z*m.z + f.w*m.w;
    }
    #pragma unroll
    for (int off = 16; off > 0; off >>= 1) {
        ff += __shfl_xor_sync(0xFFFFFFFFu, ff, off);
        fp += __shfl_xor_sync(0xFFFFFFFFu, fp, off);
    }

    if (lane == 0) {
        const float eps = 1e-12f;
        const float nf   = fmaxf(sqrtf(ff), eps);
        const float np   = fmaxf(fabsf(v) * g_proto_norm[c], eps);
        const float cosv = (v * fp) / (nf * np);
        s_part[warp] = 1.0f - cosv;
    }
    __syncthreads();

    if (threadIdx.x == 0) {
        float s = 0.0f;
        #pragma unroll
        for (int w = 0; w < WPB; w++) s += s_part[w];
        atomicAdd(out, s / (float)N);
    }
}

extern "C" void kernel_launch(void* const* d_in, const int* in_sizes, int n_in,
                              void* d_out, int out_size)
{
    const float* features   = (const float*)d_in[0];
    const float* labels     = (const float*)d_in[1];
    const float* mean_class = (const float*)d_in[2];
    float* out = (float*)d_out;

    const int N = in_sizes[0] / EMBED;   // 32768

    proto_norm_kernel<<<(N_CLASSES * 32 + THREADS - 1) / THREADS, THREADS>>>(
        mean_class, out);
    angular_loss_kernel<<<N / WPB, THREADS>>>(
        features, labels, mean_class, out, N);
}